// round 1
// baseline (speedup 1.0000x reference)
#include <cuda_runtime.h>
#include <cuda_bf16.h>

// Problem constants
#define EMBED_DIM   256
#define D4          64          // EMBED_DIM / 4 (float4 chunks per row)
#define BATCH       8192
#define L_NODE      16
#define L_EDGE      15
#define L_TOTAL     47          // 16 + 15 + 16
#define NNZ         8
#define ROWS_PER_BLOCK 16

// Precomputed positional-encoding table: 16 positions x 256 dims (16 KB).
__device__ float g_pe[L_NODE * EMBED_DIM];

// Tiny pre-kernel: 16 blocks x 128 threads, each thread one (sin, cos) pair.
__global__ void pe_init_kernel() {
    const int l = blockIdx.x;        // 0..15
    const int j = threadIdx.x;       // 0..127  -> dim pair (2j, 2j+1)
    // div_j = exp(-(2j) * ln(10000)/256)
    const float k = 9.210340371976184f / 256.0f;   // ln(10000)/256
    float div = __expf(-(float)(2 * j) * k);
    float s, c;
    sincosf((float)l * div, &s, &c);
    g_pe[l * EMBED_DIM + 2 * j]     = s;
    g_pe[l * EMBED_DIM + 2 * j + 1] = c;
}

__device__ __forceinline__ float4 f4_add(float4 a, float4 b) {
    return make_float4(a.x + b.x, a.y + b.y, a.z + b.z, a.w + b.w);
}

__global__ __launch_bounds__(256, 8)
void embed_kernel(const int*    __restrict__ node_idx,   // [16, 8192]
                  const int*    __restrict__ edge_idx,   // [15, 8192]
                  const int*    __restrict__ val_idx,    // [16*8192, 8]
                  const float*  __restrict__ val_w,      // [16*8192, 8]
                  const float4* __restrict__ node_tab,   // [128, 64]
                  const float4* __restrict__ edge_tab,   // [32, 64]
                  const float4* __restrict__ val_tab,    // [10000, 64]
                  float4*       __restrict__ out)        // [47, 8192, 64]
{
    const int l     = blockIdx.y;                 // 0..46
    const int col4  = threadIdx.x & 63;           // float4 column within row
    const int lrow  = threadIdx.x >> 6;           // 0..3 local row
    const int bbase = blockIdx.x * ROWS_PER_BLOCK;

    int pos, sec;
    if (l < L_NODE)                { sec = 0; pos = l; }
    else if (l < L_NODE + L_EDGE)  { sec = 1; pos = l - L_NODE; }
    else                           { sec = 2; pos = l - (L_NODE + L_EDGE); }

    // PE chunk for this (pos, col4) — broadcast L1/L2 hit.
    const float4 pe = reinterpret_cast<const float4*>(g_pe)[pos * D4 + col4];

    float4* outsec = out + (size_t)l * BATCH * D4;

    if (sec == 0) {
        const int* idxrow = node_idx + pos * BATCH;
        #pragma unroll
        for (int rr = 0; rr < ROWS_PER_BLOCK / 4; rr++) {
            const int b   = bbase + rr * 4 + lrow;
            const int idx = __ldg(idxrow + b);
            float4 v = __ldg(node_tab + idx * D4 + col4);
            outsec[(size_t)b * D4 + col4] = f4_add(v, pe);
        }
    } else if (sec == 1) {
        const int* idxrow = edge_idx + pos * BATCH;
        #pragma unroll
        for (int rr = 0; rr < ROWS_PER_BLOCK / 4; rr++) {
            const int b   = bbase + rr * 4 + lrow;
            const int idx = __ldg(idxrow + b);
            float4 v = __ldg(edge_tab + idx * D4 + col4);
            outsec[(size_t)b * D4 + col4] = f4_add(v, pe);
        }
    } else {
        #pragma unroll
        for (int rr = 0; rr < ROWS_PER_BLOCK / 4; rr++) {
            const int b = bbase + rr * 4 + lrow;
            const int n = pos * BATCH + b;                 // row into sparse mat
            const int*   ip = val_idx + (size_t)n * NNZ;
            const float* wp = val_w   + (size_t)n * NNZ;
            float4 acc = pe;
            #pragma unroll
            for (int kk = 0; kk < NNZ; kk++) {
                const int   idx = __ldg(ip + kk);
                const float w   = __ldg(wp + kk);
                float4 v = __ldg(val_tab + (size_t)idx * D4 + col4);
                acc.x += w * v.x;
                acc.y += w * v.y;
                acc.z += w * v.z;
                acc.w += w * v.w;
            }
            outsec[(size_t)b * D4 + col4] = acc;
        }
    }
}

extern "C" void kernel_launch(void* const* d_in, const int* in_sizes, int n_in,
                              void* d_out, int out_size) {
    const int*   node_idx = (const int*)  d_in[0];   // [16, 8192]
    const int*   edge_idx = (const int*)  d_in[1];   // [15, 8192]
    const int*   val_idx  = (const int*)  d_in[2];   // [131072, 8]
    const float* val_w    = (const float*)d_in[3];   // [131072, 8]
    const float* node_tab = (const float*)d_in[4];   // [128, 256]
    const float* edge_tab = (const float*)d_in[5];   // [32, 256]
    const float* val_tab  = (const float*)d_in[6];   // [10000, 256]
    float* out = (float*)d_out;                      // [47, 8192, 256]

    (void)in_sizes; (void)n_in; (void)out_size;

    pe_init_kernel<<<L_NODE, 128>>>();

    dim3 grid(BATCH / ROWS_PER_BLOCK, L_TOTAL);      // (512, 47)
    embed_kernel<<<grid, 256>>>(node_idx, edge_idx, val_idx, val_w,
                                (const float4*)node_tab,
                                (const float4*)edge_tab,
                                (const float4*)val_tab,
                                (float4*)out);
}